// round 6
// baseline (speedup 1.0000x reference)
#include <cuda_runtime.h>
#include <cuda_bf16.h>
#include <math.h>
#include <stddef.h>
#include <stdint.h>

#define NR 2048
#define DD 2048
#define NCLS 9
#define NBB 36

// ---- scratch (device globals: allocation-free rule) ----
__device__ float g_A[NR * DD];                 // feat / x3 (fp32 residual)
__device__ float g_B[NR * DD];                 // x2 (fp32 residual)
__device__ float g_T[NR * DD];                 // logits fp32; reused as head partials
__device__ __nv_bfloat16 g_Xb[NR * DD];        // current layer input x (bf16, row-major)
__device__ __nv_bfloat16 g_XNb[NR * DD];       // normalized feats (bf16)
__device__ __nv_bfloat16 g_Mb[NR * NR];        // cosine matrix (bf16)
__device__ uint8_t g_P8[NR * NR];              // softmax probs (e4m3, x256)
__device__ uint8_t g_Wt8[DD * DD];             // Wt (e4m3, x256)
__device__ uint8_t g_Wr8[DD * DD];             // Wr (e4m3, x256)

// =====================================================================
// helpers
// =====================================================================
__device__ __forceinline__ uint32_t smem_u32(const void* p) {
    uint32_t a;
    asm("{ .reg .u64 t; cvta.to.shared.u64 t, %1; cvt.u32.u64 %0, t; }"
        : "=r"(a) : "l"(p));
    return a;
}
__device__ __forceinline__ uint32_t pack2(float lo, float hi) {
    uint32_t r;
    asm("cvt.rn.bf16x2.f32 %0, %1, %2;" : "=r"(r) : "f"(hi), "f"(lo));
    return r;
}
__device__ __forceinline__ uint32_t pack4_e4m3(float v0, float v1, float v2, float v3) {
    uint16_t lo, hi;
    asm("cvt.rn.satfinite.e4m3x2.f32 %0, %1, %2;" : "=h"(lo) : "f"(v1), "f"(v0));
    asm("cvt.rn.satfinite.e4m3x2.f32 %0, %1, %2;" : "=h"(hi) : "f"(v3), "f"(v2));
    return ((uint32_t)hi << 16) | (uint32_t)lo;
}
#define CP_ASYNC16(dst, src) \
    asm volatile("cp.async.ca.shared.global [%0], [%1], 16;" :: "r"(dst), "l"(src) : "memory")
#define CP_COMMIT() asm volatile("cp.async.commit_group;" ::: "memory")
#define CP_WAIT(n)  asm volatile("cp.async.wait_group %0;" :: "n"(n) : "memory")
#define LDMATRIX_X4(r, addr)                                              \
    asm volatile("ldmatrix.sync.aligned.m8n8.x4.shared.b16 "              \
                 "{%0,%1,%2,%3}, [%4];"                                   \
                 : "=r"((r)[0]), "=r"((r)[1]), "=r"((r)[2]), "=r"((r)[3]) \
                 : "r"(addr))
#define LDMATRIX_X4_T(r, addr)                                            \
    asm volatile("ldmatrix.sync.aligned.m8n8.x4.trans.shared.b16 "        \
                 "{%0,%1,%2,%3}, [%4];"                                   \
                 : "=r"((r)[0]), "=r"((r)[1]), "=r"((r)[2]), "=r"((r)[3]) \
                 : "r"(addr))

__device__ __forceinline__ void mma_bf16(float* c, const uint32_t* a, const uint32_t* b) {
    asm volatile(
        "mma.sync.aligned.m16n8k16.row.col.f32.bf16.bf16.f32 "
        "{%0,%1,%2,%3}, {%4,%5,%6,%7}, {%8,%9}, {%0,%1,%2,%3};"
        : "+f"(c[0]), "+f"(c[1]), "+f"(c[2]), "+f"(c[3])
        : "r"(a[0]), "r"(a[1]), "r"(a[2]), "r"(a[3]), "r"(b[0]), "r"(b[1]));
}
__device__ __forceinline__ void mma_e4m3(float* c, const uint32_t* a, const uint32_t* b) {
    asm volatile(
        "mma.sync.aligned.m16n8k32.row.col.f32.e4m3.e4m3.f32 "
        "{%0,%1,%2,%3}, {%4,%5,%6,%7}, {%8,%9}, {%0,%1,%2,%3};"
        : "+f"(c[0]), "+f"(c[1]), "+f"(c[2]), "+f"(c[3])
        : "r"(a[0]), "r"(a[1]), "r"(a[2]), "r"(a[3]), "r"(b[0]), "r"(b[1]));
}

#define STG 16384   // bytes per operand per stage

// =====================================================================
// AvgPool2d(7,7): [N, D, 7, 7] -> [N, D] fp32 + bf16
// =====================================================================
__global__ void avgpool_kernel(const float* __restrict__ x, float* __restrict__ out,
                               __nv_bfloat16* __restrict__ outb) {
    __shared__ float s[128 * 49];
    size_t block0 = (size_t)blockIdx.x * 128;
    const float4* src = reinterpret_cast<const float4*>(x + block0 * 49);
    float4* dst = reinterpret_cast<float4*>(s);
    for (int i = threadIdx.x; i < 128 * 49 / 4; i += 256) dst[i] = src[i];
    __syncthreads();
    if (threadIdx.x < 128) {
        float sum = 0.f;
        #pragma unroll
        for (int k = 0; k < 49; k++) sum += s[threadIdx.x * 49 + k];
        float m = sum * (1.f / 49.f);
        out[block0 + threadIdx.x] = m;
        outb[block0 + threadIdx.x] = __float2bfloat16_rn(m);
    }
}

// =====================================================================
// fp32 -> e4m3 (x256) weight convert, 8 elems/thread
// =====================================================================
__global__ void f2e_kernel(const float* __restrict__ in, uint8_t* __restrict__ out) {
    size_t i = ((size_t)blockIdx.x * 256 + threadIdx.x) * 8;
    const float4 a = *(const float4*)(in + i);
    const float4 b = *(const float4*)(in + i + 4);
    uint2 o;
    o.x = pack4_e4m3(a.x * 256.f, a.y * 256.f, a.z * 256.f, a.w * 256.f);
    o.y = pack4_e4m3(b.x * 256.f, b.y * 256.f, b.z * 256.f, b.w * 256.f);
    *(uint2*)(out + i) = o;
}

// =====================================================================
// Row L2-normalize -> bf16
// =====================================================================
__global__ void normalize_kernel(const float* __restrict__ f, __nv_bfloat16* __restrict__ fn) {
    __shared__ float red[256];
    int row = blockIdx.x, t = threadIdx.x;
    const float4* p = reinterpret_cast<const float4*>(f + (size_t)row * DD);
    float4 v0 = p[2 * t], v1 = p[2 * t + 1];
    float s = v0.x * v0.x + v0.y * v0.y + v0.z * v0.z + v0.w * v0.w
            + v1.x * v1.x + v1.y * v1.y + v1.z * v1.z + v1.w * v1.w;
    red[t] = s;
    __syncthreads();
    for (int o = 128; o; o >>= 1) {
        if (t < o) red[t] += red[t + o];
        __syncthreads();
    }
    float inv = 1.f / fmaxf(sqrtf(red[0]), 1e-8f);
    uint4 o;
    o.x = pack2(v0.x * inv, v0.y * inv);
    o.y = pack2(v0.z * inv, v0.w * inv);
    o.z = pack2(v1.x * inv, v1.y * inv);
    o.w = pack2(v1.z * inv, v1.w * inv);
    *(uint4*)(fn + (size_t)row * DD + t * 8) = o;
}

// =====================================================================
// Row softmax: fp32 in -> e4m3 (x256) out
// =====================================================================
__global__ void softmax_kernel(const float* __restrict__ in, uint8_t* __restrict__ out8) {
    __shared__ float red[256];
    int row = blockIdx.x, t = threadIdx.x;
    const float4* p = reinterpret_cast<const float4*>(in + (size_t)row * NR);
    float4 u0 = p[2 * t], u1 = p[2 * t + 1];
    float v[8] = {u0.x, u0.y, u0.z, u0.w, u1.x, u1.y, u1.z, u1.w};
    float mx = v[0];
    #pragma unroll
    for (int i = 1; i < 8; i++) mx = fmaxf(mx, v[i]);
    red[t] = mx;
    __syncthreads();
    for (int o = 128; o; o >>= 1) {
        if (t < o) red[t] = fmaxf(red[t], red[t + o]);
        __syncthreads();
    }
    mx = red[0];
    __syncthreads();
    float s = 0.f;
    #pragma unroll
    for (int i = 0; i < 8; i++) {
        v[i] = __expf(v[i] - mx);
        s += v[i];
    }
    red[t] = s;
    __syncthreads();
    for (int o = 128; o; o >>= 1) {
        if (t < o) red[t] += red[t + o];
        __syncthreads();
    }
    float inv = 256.f / red[0];
    uint2 o;
    o.x = pack4_e4m3(v[0] * inv, v[1] * inv, v[2] * inv, v[3] * inv);
    o.y = pack4_e4m3(v[4] * inv, v[5] * inv, v[6] * inv, v[7] * inv);
    *(uint2*)(out8 + (size_t)row * NR + t * 8) = o;
}

// =====================================================================
// Cosine GEMM: bf16 NT, symmetric-triangular grid, bf16 out.
// C[m,n] = sum_k XN[m,k]*XN[n,k]
// =====================================================================
__device__ __forceinline__ void load_nt(uint32_t sb32,
                                        const __nv_bfloat16* A, const __nv_bfloat16* B,
                                        int bm0, int bn0, int k0, int buf, int t) {
    const int ch = t & 7;
    const int r0 = t >> 3;
    const uint32_t abase = sb32 + (uint32_t)buf * (2 * STG);
    #pragma unroll
    for (int p = 0; p < 4; p++) {
        const int row = r0 + p * 32;
        uint32_t o = (uint32_t)row * 128 + ch * 16;
        uint32_t sw = o ^ ((o >> 3) & 0x70);
        CP_ASYNC16(abase + sw, A + (size_t)(bm0 + row) * DD + k0 + ch * 8);
        CP_ASYNC16(abase + STG + sw, B + (size_t)(bn0 + row) * DD + k0 + ch * 8);
    }
}

__global__ __launch_bounds__(256, 2)
void gemm_cos(const __nv_bfloat16* __restrict__ XN, __nv_bfloat16* __restrict__ C) {
    extern __shared__ char dynsm[];
    char* sb = (char*)(((uintptr_t)dynsm + 1023) & ~(uintptr_t)1023);
    const uint32_t sb32 = smem_u32(sb);
    const int t = threadIdx.x;
    const int lane = t & 31, wid = t >> 5;
    const int wm = (wid & 3) * 32;
    const int wn = (wid >> 2) * 64;

    int rem = blockIdx.x, i = 0;
    while (rem >= 16 - i) { rem -= 16 - i; i++; }
    const int bm0 = i * 128;
    const int bn0 = (i + rem) * 128;

    float acc[2][8][4];
    #pragma unroll
    for (int a = 0; a < 2; a++)
        #pragma unroll
        for (int b = 0; b < 8; b++)
            #pragma unroll
            for (int q = 0; q < 4; q++) acc[a][b][q] = 0.f;

    load_nt(sb32, XN, XN, bm0, bn0, 0, 0, t);
    CP_COMMIT();

    const int a_row_l = lane & 15;
    const int a_kb = (lane >> 4) * 16;
    const int b_row_l = ((lane >> 4) << 3) + (lane & 7);
    const int b_kb = ((lane >> 3) & 1) * 16;

    for (int s = 0; s < 32; s++) {
        if (s < 31) {
            load_nt(sb32, XN, XN, bm0, bn0, (s + 1) * 64, (s + 1) & 1, t);
            CP_COMMIT();
            CP_WAIT(1);
        } else {
            CP_WAIT(0);
        }
        __syncthreads();
        const uint32_t aB = sb32 + (uint32_t)(s & 1) * (2 * STG);
        const uint32_t bB = aB + STG;
        #pragma unroll
        for (int kk = 0; kk < 4; kk++) {
            const int kb = kk * 32;
            uint32_t af[2][4], bf[4][4];
            #pragma unroll
            for (int mt = 0; mt < 2; mt++) {
                uint32_t o = (uint32_t)(wm + mt * 16 + a_row_l) * 128 + kb + a_kb;
                LDMATRIX_X4(af[mt], aB + (o ^ ((o >> 3) & 0x70)));
            }
            #pragma unroll
            for (int nt2 = 0; nt2 < 4; nt2++) {
                uint32_t o = (uint32_t)(wn + nt2 * 16 + b_row_l) * 128 + kb + b_kb;
                LDMATRIX_X4(bf[nt2], bB + (o ^ ((o >> 3) & 0x70)));
            }
            #pragma unroll
            for (int mt = 0; mt < 2; mt++)
                #pragma unroll
                for (int nt2 = 0; nt2 < 4; nt2++) {
                    mma_bf16(acc[mt][nt2 * 2 + 0], af[mt], &bf[nt2][0]);
                    mma_bf16(acc[mt][nt2 * 2 + 1], af[mt], &bf[nt2][2]);
                }
        }
        __syncthreads();
    }

    const int g = lane >> 2;
    const int c2 = (lane & 3) * 2;
    #pragma unroll
    for (int mt = 0; mt < 2; mt++) {
        const int row0 = bm0 + wm + mt * 16 + g;
        #pragma unroll
        for (int nt = 0; nt < 8; nt++) {
            const int col0 = bn0 + wn + nt * 8 + c2;
            float v0 = acc[mt][nt][0], v1 = acc[mt][nt][1];
            float v2 = acc[mt][nt][2], v3 = acc[mt][nt][3];
            *(uint32_t*)&C[(size_t)row0 * DD + col0] = pack2(v0, v1);
            *(uint32_t*)&C[(size_t)(row0 + 8) * DD + col0] = pack2(v2, v3);
            if (bm0 != bn0) {
                C[(size_t)col0 * DD + row0] = __float2bfloat16_rn(v0);
                C[(size_t)(col0 + 1) * DD + row0] = __float2bfloat16_rn(v1);
                C[(size_t)col0 * DD + row0 + 8] = __float2bfloat16_rn(v2);
                C[(size_t)(col0 + 1) * DD + row0 + 8] = __float2bfloat16_rn(v3);
            }
        }
    }
}

// =====================================================================
// NN GEMM (bf16): C[m,n] = sum_k M[m,k] * X[k,n]  -> fp32 out
// A as before; B tile [64 k][128 n] bf16 (256B rows), ldmatrix.trans.
// swizzle: o ^ (((o>>8)&7)<<5)
// =====================================================================
__global__ __launch_bounds__(256, 2)
void gemm_nn(const __nv_bfloat16* __restrict__ A, const __nv_bfloat16* __restrict__ X,
             float* __restrict__ C) {
    extern __shared__ char dynsm[];
    char* sb = (char*)(((uintptr_t)dynsm + 1023) & ~(uintptr_t)1023);
    const uint32_t sb32 = smem_u32(sb);
    const int t = threadIdx.x;
    const int lane = t & 31, wid = t >> 5;
    const int wm = (wid & 3) * 32;
    const int wn = (wid >> 2) * 64;
    const int bm0 = blockIdx.y * 128;
    const int bn0 = blockIdx.x * 128;

    float acc[2][8][4];
    #pragma unroll
    for (int a = 0; a < 2; a++)
        #pragma unroll
        for (int b = 0; b < 8; b++)
            #pragma unroll
            for (int q = 0; q < 4; q++) acc[a][b][q] = 0.f;

    // loader lanes
    const int chA = t & 7, rA0 = t >> 3;
    const int chB = t & 15, rB0 = t >> 4;

    // stage 0
    {
        const uint32_t ab = sb32;
        #pragma unroll
        for (int p = 0; p < 4; p++) {
            const int row = rA0 + p * 32;
            uint32_t o = (uint32_t)row * 128 + chA * 16;
            CP_ASYNC16(ab + (o ^ ((o >> 3) & 0x70)), A + (size_t)(bm0 + row) * DD + chA * 8);
        }
        const uint32_t bb = sb32 + STG;
        #pragma unroll
        for (int p = 0; p < 4; p++) {
            const int row = rB0 + p * 16;
            uint32_t o = (uint32_t)row * 256 + chB * 16;
            CP_ASYNC16(bb + (o ^ (((o >> 8) & 7) << 5)), X + (size_t)row * DD + bn0 + chB * 8);
        }
    }
    CP_COMMIT();

    const int a_row_l = lane & 15;
    const int a_kb = (lane >> 4) * 16;
    const int b_k_l = ((lane >> 3) & 1) * 8 + (lane & 7);
    const int b_nb = (lane >> 4) * 16;

    for (int s = 0; s < 32; s++) {
        if (s < 31) {
            const int k0 = (s + 1) * 64;
            const int buf = (s + 1) & 1;
            const uint32_t ab = sb32 + (uint32_t)buf * (2 * STG);
            #pragma unroll
            for (int p = 0; p < 4; p++) {
                const int row = rA0 + p * 32;
                uint32_t o = (uint32_t)row * 128 + chA * 16;
                CP_ASYNC16(ab + (o ^ ((o >> 3) & 0x70)),
                           A + (size_t)(bm0 + row) * DD + k0 + chA * 8);
            }
            const uint32_t bb = ab + STG;
            #pragma unroll
            for (int p = 0; p < 4; p++) {
                const int row = rB0 + p * 16;
                uint32_t o = (uint32_t)row * 256 + chB * 16;
                CP_ASYNC16(bb + (o ^ (((o >> 8) & 7) << 5)),
                           X + (size_t)(k0 + row) * DD + bn0 + chB * 8);
            }
            CP_COMMIT();
            CP_WAIT(1);
        } else {
            CP_WAIT(0);
        }
        __syncthreads();
        const uint32_t aB = sb32 + (uint32_t)(s & 1) * (2 * STG);
        const uint32_t bB = aB + STG;
        #pragma unroll
        for (int kk = 0; kk < 4; kk++) {
            uint32_t af[2][4], bf[4][4];
            #pragma unroll
            for (int mt = 0; mt < 2; mt++) {
                uint32_t o = (uint32_t)(wm + mt * 16 + a_row_l) * 128 + kk * 32 + a_kb;
                LDMATRIX_X4(af[mt], aB + (o ^ ((o >> 3) & 0x70)));
            }
            #pragma unroll
            for (int nt2 = 0; nt2 < 4; nt2++) {
                uint32_t o = (uint32_t)(kk * 16 + b_k_l) * 256 + (wn + nt2 * 16) * 2 + b_nb;
                LDMATRIX_X4_T(bf[nt2], bB + (o ^ (((o >> 8) & 7) << 5)));
            }
            #pragma unroll
            for (int mt = 0; mt < 2; mt++)
                #pragma unroll
                for (int nt2 = 0; nt2 < 4; nt2++) {
                    mma_bf16(acc[mt][nt2 * 2 + 0], af[mt], &bf[nt2][0]);
                    mma_bf16(acc[mt][nt2 * 2 + 1], af[mt], &bf[nt2][2]);
                }
        }
        __syncthreads();
    }

    const int g = lane >> 2;
    const int c2 = (lane & 3) * 2;
    #pragma unroll
    for (int mt = 0; mt < 2; mt++) {
        const int row0 = bm0 + wm + mt * 16 + g;
        #pragma unroll
        for (int nt = 0; nt < 8; nt++) {
            const int col0 = bn0 + wn + nt * 8 + c2;
            float2 o0 = {acc[mt][nt][0], acc[mt][nt][1]};
            float2 o1 = {acc[mt][nt][2], acc[mt][nt][3]};
            *(float2*)&C[(size_t)row0 * DD + col0] = o0;
            *(float2*)&C[(size_t)(row0 + 8) * DD + col0] = o1;
        }
    }
}

// =====================================================================
// fp8 NT GEMM: C = (P8 @ W8^T) * 2^-16 + bias + res  -> fp32 (+ bf16 copy)
// BK=128 e4m3 (128B rows, same SW128 layout), m16n8k32.
// =====================================================================
__device__ __forceinline__ void load_nt8(uint32_t sb32,
                                         const uint8_t* A, const uint8_t* B,
                                         int bm0, int bn0, int k0, int buf, int t) {
    const int ch = t & 7;
    const int r0 = t >> 3;
    const uint32_t abase = sb32 + (uint32_t)buf * (2 * STG);
    #pragma unroll
    for (int p = 0; p < 4; p++) {
        const int row = r0 + p * 32;
        uint32_t o = (uint32_t)row * 128 + ch * 16;
        uint32_t sw = o ^ ((o >> 3) & 0x70);
        CP_ASYNC16(abase + sw, A + (size_t)(bm0 + row) * DD + k0 + ch * 16);
        CP_ASYNC16(abase + STG + sw, B + (size_t)(bn0 + row) * DD + k0 + ch * 16);
    }
}

template <bool OUTB>
__global__ __launch_bounds__(256, 2)
void gemm_f8(const uint8_t* __restrict__ P, const uint8_t* __restrict__ W,
             float* __restrict__ C, __nv_bfloat16* __restrict__ Cb,
             const float* __restrict__ bias, const float* __restrict__ res) {
    extern __shared__ char dynsm[];
    char* sb = (char*)(((uintptr_t)dynsm + 1023) & ~(uintptr_t)1023);
    const uint32_t sb32 = smem_u32(sb);
    const int t = threadIdx.x;
    const int lane = t & 31, wid = t >> 5;
    const int wm = (wid & 3) * 32;
    const int wn = (wid >> 2) * 64;
    const int bm0 = blockIdx.y * 128;
    const int bn0 = blockIdx.x * 128;

    float acc[2][8][4];
    #pragma unroll
    for (int a = 0; a < 2; a++)
        #pragma unroll
        for (int b = 0; b < 8; b++)
            #pragma unroll
            for (int q = 0; q < 4; q++) acc[a][b][q] = 0.f;

    load_nt8(sb32, P, W, bm0, bn0, 0, 0, t);
    CP_COMMIT();

    const int a_row_l = lane & 15;
    const int a_kb = (lane >> 4) * 16;
    const int b_row_l = ((lane >> 4) << 3) + (lane & 7);
    const int b_kb = ((lane >> 3) & 1) * 16;

    for (int s = 0; s < 16; s++) {
        if (s < 15) {
            load_nt8(sb32, P, W, bm0, bn0, (s + 1) * 128, (s + 1) & 1, t);
            CP_COMMIT();
            CP_WAIT(1);
        } else {
            CP_WAIT(0);
        }
        __syncthreads();
        const uint32_t aB = sb32 + (uint32_t)(s & 1) * (2 * STG);
        const uint32_t bB = aB + STG;
        #pragma unroll
        for (int kk = 0; kk < 4; kk++) {
            const int kb = kk * 32;
            uint32_t af[2][4], bf[4][4];
            #pragma unroll
            for (int mt = 0; mt < 2; mt++) {
                uint32_t o = (uint32_t)(wm + mt * 16 + a_row_l) * 128 + kb + a_kb;
                LDMATRIX_X4(af[mt], aB + (o ^ ((o >> 3) & 0x70)));
            }
            #pragma unroll
            for (int nt2 = 0; nt2 < 4; nt2++) {
                uint32_t o = (uint32_t)(wn + nt2 * 16 + b_row_l) * 128 + kb + b_kb;
                LDMATRIX_X4(bf[nt2], bB + (o ^ ((o >> 3) & 0x70)));
            }
            #pragma unroll
            for (int mt = 0; mt < 2; mt++)
                #pragma unroll
                for (int nt2 = 0; nt2 < 4; nt2++) {
                    mma_e4m3(acc[mt][nt2 * 2 + 0], af[mt], &bf[nt2][0]);
                    mma_e4m3(acc[mt][nt2 * 2 + 1], af[mt], &bf[nt2][2]);
                }
        }
        __syncthreads();
    }

    const int g = lane >> 2;
    const int c2 = (lane & 3) * 2;
    const float SC = 1.f / 65536.f;
    #pragma unroll
    for (int mt = 0; mt < 2; mt++) {
        const int row0 = bm0 + wm + mt * 16 + g;
        #pragma unroll
        for (int nt = 0; nt < 8; nt++) {
            const int col0 = bn0 + wn + nt * 8 + c2;
            float b0 = bias[col0], b1 = bias[col0 + 1];
            const float2 r0 = *(const float2*)&res[(size_t)row0 * DD + col0];
            const float2 r1 = *(const float2*)&res[(size_t)(row0 + 8) * DD + col0];
            float v0 = acc[mt][nt][0] * SC + b0 + r0.x;
            float v1 = acc[mt][nt][1] * SC + b1 + r0.y;
            float v2 = acc[mt][nt][2] * SC + b0 + r1.x;
            float v3 = acc[mt][nt][3] * SC + b1 + r1.y;
            float2 o0 = {v0, v1}, o1 = {v2, v3};
            *(float2*)&C[(size_t)row0 * DD + col0] = o0;
            *(float2*)&C[(size_t)(row0 + 8) * DD + col0] = o1;
            if (OUTB) {
                *(uint32_t*)&Cb[(size_t)row0 * DD + col0] = pack2(v0, v1);
                *(uint32_t*)&Cb[(size_t)(row0 + 8) * DD + col0] = pack2(v2, v3);
            }
        }
    }
}

// =====================================================================
// Head, split-K (fp32)
// =====================================================================
__global__ __launch_bounds__(256)
void head_partial(const float* __restrict__ x,
                  const float* __restrict__ Wc, const float* __restrict__ Wb,
                  float* __restrict__ part) {
    __shared__ float Wsm[48 * 64];
    __shared__ float xs[32 * 65];
    const int rb = blockIdx.x, ks = blockIdx.y;
    const int t = threadIdx.x;
    const int r = t & 31, jg = t >> 5;

    float acc[6] = {0.f, 0.f, 0.f, 0.f, 0.f, 0.f};

    for (int k0 = ks * 256; k0 < ks * 256 + 256; k0 += 64) {
        for (int i = t; i < 45 * 64; i += 256) {
            int j = i >> 6, k = i & 63;
            const float* w = (j < NCLS) ? (Wc + (size_t)j * DD)
                                        : (Wb + (size_t)(j - NCLS) * DD);
            Wsm[i] = w[k0 + k];
        }
        for (int i = t; i < 32 * 64; i += 256) {
            int rr = i >> 6, k = i & 63;
            xs[rr * 65 + k] = x[(size_t)(rb * 32 + rr) * DD + k0 + k];
        }
        __syncthreads();
        #pragma unroll 4
        for (int k = 0; k < 64; k++) {
            float xv = xs[r * 65 + k];
            #pragma unroll
            for (int u = 0; u < 6; u++) {
                int j = jg + 8 * u;
                if (j < 45) acc[u] += xv * Wsm[j * 64 + k];
            }
        }
        __syncthreads();
    }
    #pragma unroll
    for (int u = 0; u < 6; u++) {
        int j = jg + 8 * u;
        if (j < 45)
            part[((size_t)ks * NR + rb * 32 + r) * 45 + j] = acc[u];
    }
}

__global__ void head_reduce(const float* __restrict__ part,
                            const float* __restrict__ bc, const float* __restrict__ bb,
                            float* __restrict__ out) {
    int idx = blockIdx.x * 256 + threadIdx.x;
    if (idx >= NR * 45) return;
    int i = idx / 45, j = idx - i * 45;
    float s = 0.f;
    #pragma unroll
    for (int ks = 0; ks < 8; ks++) s += part[((size_t)ks * NR + i) * 45 + j];
    if (j < NCLS)
        out[(size_t)i * NCLS + j] = s + bc[j];
    else
        out[(size_t)NR * NCLS + (size_t)i * NBB + (j - NCLS)] = s + bb[j - NCLS];
}

// =====================================================================
extern "C" void kernel_launch(void* const* d_in, const int* in_sizes, int n_in,
                              void* d_out, int out_size) {
    const float* x  = (const float*)d_in[0];
    const float* Wt = (const float*)d_in[1];
    const float* bt = (const float*)d_in[2];
    const float* Wr = (const float*)d_in[3];
    const float* br = (const float*)d_in[4];
    const float* Wc = (const float*)d_in[5];
    const float* bc = (const float*)d_in[6];
    const float* Wb = (const float*)d_in[7];
    const float* bb = (const float*)d_in[8];
    float* out = (float*)d_out;

    float *A, *B, *T;
    __nv_bfloat16 *Xb, *XNb, *Mb;
    uint8_t *P8, *Wt8, *Wr8;
    cudaGetSymbolAddress((void**)&A, g_A);
    cudaGetSymbolAddress((void**)&B, g_B);
    cudaGetSymbolAddress((void**)&T, g_T);
    cudaGetSymbolAddress((void**)&Xb, g_Xb);
    cudaGetSymbolAddress((void**)&XNb, g_XNb);
    cudaGetSymbolAddress((void**)&Mb, g_Mb);
    cudaGetSymbolAddress((void**)&P8, g_P8);
    cudaGetSymbolAddress((void**)&Wt8, g_Wt8);
    cudaGetSymbolAddress((void**)&Wr8, g_Wr8);

    const int SMEM = 4 * STG + 1024;   // 66560 B
    cudaFuncSetAttribute(gemm_cos, cudaFuncAttributeMaxDynamicSharedMemorySize, SMEM);
    cudaFuncSetAttribute(gemm_nn,  cudaFuncAttributeMaxDynamicSharedMemorySize, SMEM);
    cudaFuncSetAttribute(gemm_f8<true>,  cudaFuncAttributeMaxDynamicSharedMemorySize, SMEM);
    cudaFuncSetAttribute(gemm_f8<false>, cudaFuncAttributeMaxDynamicSharedMemorySize, SMEM);

    dim3 gg(16, 16);

    avgpool_kernel<<<NR * DD / 128, 256>>>(x, A, Xb);
    f2e_kernel<<<DD * DD / 2048, 256>>>(Wt, Wt8);
    f2e_kernel<<<DD * DD / 2048, 256>>>(Wr, Wr8);

    // ---- layer 1 ----
    normalize_kernel<<<NR, 256>>>(A, XNb);
    gemm_cos<<<136, 256, SMEM>>>(XNb, Mb);
    gemm_nn<<<gg, 256, SMEM>>>(Mb, Xb, T);                 // mat @ x
    softmax_kernel<<<NR, 256>>>(T, P8);
    gemm_f8<true><<<gg, 256, SMEM>>>(P8, Wt8, B, Xb, bt, A);   // x2 = sm@Wt^T+bt+x

    // ---- layer 2 ----
    normalize_kernel<<<NR, 256>>>(B, XNb);
    gemm_cos<<<136, 256, SMEM>>>(XNb, Mb);
    gemm_nn<<<gg, 256, SMEM>>>(Mb, Xb, T);
    softmax_kernel<<<NR, 256>>>(T, P8);
    gemm_f8<false><<<gg, 256, SMEM>>>(P8, Wr8, A, nullptr, br, B);  // x3

    // ---- heads (partials into T) ----
    head_partial<<<dim3(64, 8), 256>>>(A, Wc, Wb, T);
    head_reduce<<<(NR * 45 + 255) / 256, 256>>>(T, bc, bb, out);
}

// round 7
// speedup vs baseline: 1.0161x; 1.0161x over previous
#include <cuda_runtime.h>
#include <cuda_bf16.h>
#include <math.h>
#include <stddef.h>
#include <stdint.h>

#define NR 2048
#define DD 2048
#define NCLS 9
#define NBB 36

// ---- scratch (device globals: allocation-free rule) ----
__device__ float g_A[NR * DD];                 // feat / x3 (fp32, residual)
__device__ float g_B[NR * DD];                 // x2 (fp32, residual)
__device__ float g_T[NR * DD];                 // mat@x (fp32) ; reused as head partials
__device__ __nv_bfloat16 g_XNb[NR * DD];       // normalized feats (bf16)
__device__ __nv_bfloat16 g_Mb[NR * NR];        // cosine matrix (bf16)
__device__ __nv_bfloat16 g_ATb[NR * DD];       // x^T (bf16)
__device__ __nv_bfloat16 g_Tb[NR * DD];        // softmax(mat@x) (bf16)
__device__ __nv_bfloat16 g_Wtb[DD * DD];       // Wt (bf16)
__device__ __nv_bfloat16 g_Wrb[DD * DD];       // Wr (bf16)

// =====================================================================
// helpers
// =====================================================================
__device__ __forceinline__ uint32_t smem_u32(const void* p) {
    uint32_t a;
    asm("{ .reg .u64 t; cvta.to.shared.u64 t, %1; cvt.u32.u64 %0, t; }"
        : "=r"(a) : "l"(p));
    return a;
}
__device__ __forceinline__ uint32_t pack2(float lo, float hi) {
    uint32_t r;
    asm("cvt.rn.bf16x2.f32 %0, %1, %2;" : "=r"(r) : "f"(hi), "f"(lo));
    return r;
}
#define CP_ASYNC16(dst, src) \
    asm volatile("cp.async.ca.shared.global [%0], [%1], 16;" :: "r"(dst), "l"(src) : "memory")
#define CP_COMMIT() asm volatile("cp.async.commit_group;" ::: "memory")
#define CP_WAIT(n)  asm volatile("cp.async.wait_group %0;" :: "n"(n) : "memory")
#define LDMATRIX_X4(r, addr)                                              \
    asm volatile("ldmatrix.sync.aligned.m8n8.x4.shared.b16 "              \
                 "{%0,%1,%2,%3}, [%4];"                                   \
                 : "=r"((r)[0]), "=r"((r)[1]), "=r"((r)[2]), "=r"((r)[3]) \
                 : "r"(addr))

__device__ __forceinline__ void mma_bf16(float* c, const uint32_t* a, const uint32_t* b) {
    asm volatile(
        "mma.sync.aligned.m16n8k16.row.col.f32.bf16.bf16.f32 "
        "{%0,%1,%2,%3}, {%4,%5,%6,%7}, {%8,%9}, {%0,%1,%2,%3};"
        : "+f"(c[0]), "+f"(c[1]), "+f"(c[2]), "+f"(c[3])
        : "r"(a[0]), "r"(a[1]), "r"(a[2]), "r"(a[3]), "r"(b[0]), "r"(b[1]));
}

// =====================================================================
// AvgPool2d(7,7): [N, D, 7, 7] -> [N, D]  (HBM-bound floor)
// =====================================================================
__global__ void avgpool_kernel(const float* __restrict__ x, float* __restrict__ out) {
    __shared__ float s[128 * 49];
    size_t block0 = (size_t)blockIdx.x * 128;
    const float4* src = reinterpret_cast<const float4*>(x + block0 * 49);
    float4* dst = reinterpret_cast<float4*>(s);
    for (int i = threadIdx.x; i < 128 * 49 / 4; i += 256) dst[i] = src[i];
    __syncthreads();
    if (threadIdx.x < 128) {
        float sum = 0.f;
        #pragma unroll
        for (int k = 0; k < 49; k++) sum += s[threadIdx.x * 49 + k];
        out[block0 + threadIdx.x] = sum * (1.f / 49.f);
    }
}

// =====================================================================
// fp32 -> bf16 convert (weights), 8 elems/thread
// =====================================================================
__global__ void f2b_kernel(const float* __restrict__ in, __nv_bfloat16* __restrict__ out) {
    size_t i = ((size_t)blockIdx.x * 256 + threadIdx.x) * 8;
    const float4 a = *(const float4*)(in + i);
    const float4 b = *(const float4*)(in + i + 4);
    uint4 o;
    o.x = pack2(a.x, a.y); o.y = pack2(a.z, a.w);
    o.z = pack2(b.x, b.y); o.w = pack2(b.z, b.w);
    *(uint4*)(out + i) = o;
}

// =====================================================================
// Row L2-normalize -> bf16: xn[i,:] = x[i,:] / max(||x||, 1e-8)
// =====================================================================
__global__ void normalize_kernel(const float* __restrict__ f, __nv_bfloat16* __restrict__ fn) {
    __shared__ float red[256];
    int row = blockIdx.x, t = threadIdx.x;
    const float4* p = reinterpret_cast<const float4*>(f + (size_t)row * DD);
    float4 v0 = p[2 * t], v1 = p[2 * t + 1];
    float s = v0.x * v0.x + v0.y * v0.y + v0.z * v0.z + v0.w * v0.w
            + v1.x * v1.x + v1.y * v1.y + v1.z * v1.z + v1.w * v1.w;
    red[t] = s;
    __syncthreads();
    for (int o = 128; o; o >>= 1) {
        if (t < o) red[t] += red[t + o];
        __syncthreads();
    }
    float inv = 1.f / fmaxf(sqrtf(red[0]), 1e-8f);
    uint4 o;
    o.x = pack2(v0.x * inv, v0.y * inv);
    o.y = pack2(v0.z * inv, v0.w * inv);
    o.z = pack2(v1.x * inv, v1.y * inv);
    o.w = pack2(v1.z * inv, v1.w * inv);
    *(uint4*)(fn + (size_t)row * DD + t * 8) = o;
}

// =====================================================================
// Row softmax: read fp32 [NR,2048], write bf16
// =====================================================================
__global__ void softmax_kernel(const float* __restrict__ in, __nv_bfloat16* __restrict__ outb) {
    __shared__ float red[256];
    int row = blockIdx.x, t = threadIdx.x;
    const float4* p = reinterpret_cast<const float4*>(in + (size_t)row * NR);
    float4 u0 = p[2 * t], u1 = p[2 * t + 1];
    float v[8] = {u0.x, u0.y, u0.z, u0.w, u1.x, u1.y, u1.z, u1.w};
    float mx = v[0];
    #pragma unroll
    for (int i = 1; i < 8; i++) mx = fmaxf(mx, v[i]);
    red[t] = mx;
    __syncthreads();
    for (int o = 128; o; o >>= 1) {
        if (t < o) red[t] = fmaxf(red[t], red[t + o]);
        __syncthreads();
    }
    mx = red[0];
    __syncthreads();
    float s = 0.f;
    #pragma unroll
    for (int i = 0; i < 8; i++) {
        v[i] = __expf(v[i] - mx);
        s += v[i];
    }
    red[t] = s;
    __syncthreads();
    for (int o = 128; o; o >>= 1) {
        if (t < o) red[t] += red[t + o];
        __syncthreads();
    }
    float inv = 1.f / red[0];
    uint4 o;
    o.x = pack2(v[0] * inv, v[1] * inv);
    o.y = pack2(v[2] * inv, v[3] * inv);
    o.z = pack2(v[4] * inv, v[5] * inv);
    o.w = pack2(v[6] * inv, v[7] * inv);
    *(uint4*)(outb + (size_t)row * NR + t * 8) = o;
}

// =====================================================================
// 32x32 tiled transpose: out(bf16) = in(fp32)^T
// =====================================================================
__global__ void transpose_kernel(const float* __restrict__ in, __nv_bfloat16* __restrict__ out) {
    __shared__ float tile[32][33];
    int x = blockIdx.x * 32 + threadIdx.x;
    int y = blockIdx.y * 32 + threadIdx.y;
    #pragma unroll
    for (int j = 0; j < 32; j += 8)
        tile[threadIdx.y + j][threadIdx.x] = in[(size_t)(y + j) * DD + x];
    __syncthreads();
    x = blockIdx.y * 32 + threadIdx.x;
    y = blockIdx.x * 32 + threadIdx.y;
    #pragma unroll
    for (int j = 0; j < 32; j += 8)
        out[(size_t)(y + j) * DD + x] = __float2bfloat16_rn(tile[threadIdx.x][threadIdx.y + j]);
}

// =====================================================================
// bf16 NT GEMM via ldmatrix + mma.m16n8k16: C[m,n] = sum_k A[m,k]*B[n,k]
// 128x128 CTA tile, 256 thr (8 warps @ 32x64), BK=64, cp.async 3-stage
// pipeline, ONE __syncthreads per stage. bf16 smem, SW128 swizzle.
// EPI: 0 plain | 2 (+bias[c]+res[r,c]).  SYM: triangular grid + mirror.
// OUTBF: write C as bf16.
// =====================================================================
#define STG 16384   // bytes per operand per stage (128 rows * 128B)
#define NSTAGE 3

__device__ __forceinline__ void load_stage(uint32_t sb32,
                                           const __nv_bfloat16* A, const __nv_bfloat16* B,
                                           int bm0, int bn0, int k0, int buf, int t) {
    const int ch = t & 7;        // 16B chunk within 128B row
    const int r0 = t >> 3;       // 0..31
    const uint32_t abase = sb32 + (uint32_t)buf * (2 * STG);
    #pragma unroll
    for (int p = 0; p < 4; p++) {
        const int row = r0 + p * 32;
        uint32_t o = (uint32_t)row * 128 + ch * 16;
        uint32_t sw = o ^ ((o >> 3) & 0x70);
        CP_ASYNC16(abase + sw, A + (size_t)(bm0 + row) * DD + k0 + ch * 8);
        CP_ASYNC16(abase + STG + sw, B + (size_t)(bn0 + row) * DD + k0 + ch * 8);
    }
}

template <int EPI, bool SYM, bool OUTBF>
__global__ __launch_bounds__(256, 2)
void gemm_bf16(const __nv_bfloat16* __restrict__ A, const __nv_bfloat16* __restrict__ B,
               void* __restrict__ Cv,
               const float* __restrict__ bias,
               const float* __restrict__ res) {
    extern __shared__ char dynsm[];
    char* sb = (char*)(((uintptr_t)dynsm + 1023) & ~(uintptr_t)1023);
    const uint32_t sb32 = smem_u32(sb);

    const int t = threadIdx.x;
    const int lane = t & 31, wid = t >> 5;
    const int wm = (wid & 3) * 32;
    const int wn = (wid >> 2) * 64;

    int bm0, bn0;
    if (SYM) {
        int rem = blockIdx.x, i = 0;
        while (rem >= 16 - i) { rem -= 16 - i; i++; }
        bm0 = i * 128;
        bn0 = (i + rem) * 128;
    } else {
        bm0 = blockIdx.y * 128;
        bn0 = blockIdx.x * 128;
    }

    float acc[2][8][4];
    #pragma unroll
    for (int i = 0; i < 2; i++)
        #pragma unroll
        for (int j = 0; j < 8; j++)
            #pragma unroll
            for (int q = 0; q < 4; q++) acc[i][j][q] = 0.f;

    // prologue: stages 0 and 1 in flight
    load_stage(sb32, A, B, bm0, bn0, 0, 0, t);
    CP_COMMIT();
    load_stage(sb32, A, B, bm0, bn0, 64, 1, t);
    CP_COMMIT();

    // ldmatrix lane addressing
    const int a_row_l = lane & 15;
    const int a_kb = (lane >> 4) * 16;            // 0 or 16 bytes
    const int b_row_l = ((lane >> 4) << 3) + (lane & 7);
    const int b_kb = ((lane >> 3) & 1) * 16;

    int buf = 0;
    for (int s = 0; s < 32; s++) {
        if (s < 31) { CP_WAIT(1); } else { CP_WAIT(0); }
        __syncthreads();
        // issue stage s+2 BEFORE compute so it overlaps the MMAs.
        if (s < 30) {
            int nb = buf + 2; if (nb >= NSTAGE) nb -= NSTAGE;
            load_stage(sb32, A, B, bm0, bn0, (s + 2) * 64, nb, t);
            CP_COMMIT();
        }

        const uint32_t aB = sb32 + (uint32_t)buf * (2 * STG);
        const uint32_t bB = aB + STG;
        #pragma unroll
        for (int kk = 0; kk < 4; kk++) {
            const int kb = kk * 32;               // 16 k-elems = 32B
            uint32_t af[2][4], bf[4][4];
            #pragma unroll
            for (int mt = 0; mt < 2; mt++) {
                uint32_t o = (uint32_t)(wm + mt * 16 + a_row_l) * 128 + kb + a_kb;
                LDMATRIX_X4(af[mt], aB + (o ^ ((o >> 3) & 0x70)));
            }
            #pragma unroll
            for (int nt2 = 0; nt2 < 4; nt2++) {
                uint32_t o = (uint32_t)(wn + nt2 * 16 + b_row_l) * 128 + kb + b_kb;
                LDMATRIX_X4(bf[nt2], bB + (o ^ ((o >> 3) & 0x70)));
            }
            #pragma unroll
            for (int mt = 0; mt < 2; mt++)
                #pragma unroll
                for (int nt2 = 0; nt2 < 4; nt2++) {
                    mma_bf16(acc[mt][nt2 * 2 + 0], af[mt], &bf[nt2][0]);
                    mma_bf16(acc[mt][nt2 * 2 + 1], af[mt], &bf[nt2][2]);
                }
        }
        if (++buf == NSTAGE) buf = 0;
    }

    // ---- epilogue ----
    const int g = lane >> 2;
    const int c2 = (lane & 3) * 2;
    float* Cf = (float*)Cv;
    __nv_bfloat16* Cb = (__nv_bfloat16*)Cv;

    #pragma unroll
    for (int mt = 0; mt < 2; mt++) {
        const int row0 = bm0 + wm + mt * 16 + g;
        #pragma unroll
        for (int nt = 0; nt < 8; nt++) {
            const int col0 = bn0 + wn + nt * 8 + c2;
            float v0 = acc[mt][nt][0], v1 = acc[mt][nt][1];
            float v2 = acc[mt][nt][2], v3 = acc[mt][nt][3];
            if (EPI == 2) {
                float b0 = bias[col0], b1 = bias[col0 + 1];
                const float2 r0 = *(const float2*)&res[(size_t)row0 * DD + col0];
                const float2 r1 = *(const float2*)&res[(size_t)(row0 + 8) * DD + col0];
                v0 += b0 + r0.x; v1 += b1 + r0.y;
                v2 += b0 + r1.x; v3 += b1 + r1.y;
            }
            if (OUTBF) {
                *(uint32_t*)&Cb[(size_t)row0 * DD + col0] = pack2(v0, v1);
                *(uint32_t*)&Cb[(size_t)(row0 + 8) * DD + col0] = pack2(v2, v3);
                if (SYM && bm0 != bn0) {
                    Cb[(size_t)col0 * DD + row0] = __float2bfloat16_rn(v0);
                    Cb[(size_t)(col0 + 1) * DD + row0] = __float2bfloat16_rn(v1);
                    Cb[(size_t)col0 * DD + row0 + 8] = __float2bfloat16_rn(v2);
                    Cb[(size_t)(col0 + 1) * DD + row0 + 8] = __float2bfloat16_rn(v3);
                }
            } else {
                float2 o0 = {v0, v1}, o1 = {v2, v3};
                *(float2*)&Cf[(size_t)row0 * DD + col0] = o0;
                *(float2*)&Cf[(size_t)(row0 + 8) * DD + col0] = o1;
            }
        }
    }
}

// =====================================================================
// Head, split-K: part[ks][row][j] = sum_{k in ks} x[row,k]*W_all[j,k]
// =====================================================================
__global__ __launch_bounds__(256)
void head_partial(const float* __restrict__ x,
                  const float* __restrict__ Wc, const float* __restrict__ Wb,
                  float* __restrict__ part) {
    __shared__ float Wsm[48 * 64];
    __shared__ float xs[32 * 65];
    const int rb = blockIdx.x, ks = blockIdx.y;
    const int t = threadIdx.x;
    const int r = t & 31, jg = t >> 5;

    float acc[6] = {0.f, 0.f, 0.f, 0.f, 0.f, 0.f};

    for (int k0 = ks * 256; k0 < ks * 256 + 256; k0 += 64) {
        for (int i = t; i < 45 * 64; i += 256) {
            int j = i >> 6, k = i & 63;
            const float* w = (j < NCLS) ? (Wc + (size_t)j * DD)
                                        : (Wb + (size_t)(j - NCLS) * DD);
            Wsm[i] = w[k0 + k];
        }
        for (int i = t; i < 32 * 64; i += 256) {
            int rr = i >> 6, k = i & 63;
            xs[rr * 65 + k] = x[(size_t)(rb * 32 + rr) * DD + k0 + k];
        }
        __syncthreads();
        #pragma unroll 4
        for (int k = 0; k < 64; k++) {
            float xv = xs[r * 65 + k];
            #pragma unroll
            for (int u = 0; u < 6; u++) {
                int j = jg + 8 * u;
                if (j < 45) acc[u] += xv * Wsm[j * 64 + k];
            }
        }
        __syncthreads();
    }
    #pragma unroll
    for (int u = 0; u < 6; u++) {
        int j = jg + 8 * u;
        if (j < 45)
            part[((size_t)ks * NR + rb * 32 + r) * 45 + j] = acc[u];
    }
}

__global__ void head_reduce(const float* __restrict__ part,
                            const float* __restrict__ bc, const float* __restrict__ bb,
                            float* __restrict__ out) {
    int idx = blockIdx.x * 256 + threadIdx.x;
    if (idx >= NR * 45) return;
    int i = idx / 45, j = idx - i * 45;
    float s = 0.f;
    #pragma unroll
    for (int ks = 0; ks < 8; ks++) s += part[((size_t)ks * NR + i) * 45 + j];
    if (j < NCLS)
        out[(size_t)i * NCLS + j] = s + bc[j];
    else
        out[(size_t)NR * NCLS + (size_t)i * NBB + (j - NCLS)] = s + bb[j - NCLS];
}

// =====================================================================
extern "C" void kernel_launch(void* const* d_in, const int* in_sizes, int n_in,
                              void* d_out, int out_size) {
    const float* x  = (const float*)d_in[0];
    const float* Wt = (const float*)d_in[1];
    const float* bt = (const float*)d_in[2];
    const float* Wr = (const float*)d_in[3];
    const float* br = (const float*)d_in[4];
    const float* Wc = (const float*)d_in[5];
    const float* bc = (const float*)d_in[6];
    const float* Wb = (const float*)d_in[7];
    const float* bb = (const float*)d_in[8];
    float* out = (float*)d_out;

    float *A, *B, *T;
    __nv_bfloat16 *XNb, *Mb, *ATb, *Tb, *Wtb, *Wrb;
    cudaGetSymbolAddress((void**)&A, g_A);
    cudaGetSymbolAddress((void**)&B, g_B);
    cudaGetSymbolAddress((void**)&T, g_T);
    cudaGetSymbolAddress((void**)&XNb, g_XNb);
    cudaGetSymbolAddress((void**)&Mb, g_Mb);
    cudaGetSymbolAddress((void**)&ATb, g_ATb);
    cudaGetSymbolAddress((void**)&Tb, g_Tb);
    cudaGetSymbolAddress((void**)&Wtb, g_Wtb);
    cudaGetSymbolAddress((void**)&Wrb, g_Wrb);

    const int SMEM = NSTAGE * 2 * STG + 1024;   // 99328 B
    cudaFuncSetAttribute(gemm_bf16<0, false, false>, cudaFuncAttributeMaxDynamicSharedMemorySize, SMEM);
    cudaFuncSetAttribute(gemm_bf16<2, false, false>, cudaFuncAttributeMaxDynamicSharedMemorySize, SMEM);
    cudaFuncSetAttribute(gemm_bf16<0, true, true>,   cudaFuncAttributeMaxDynamicSharedMemorySize, SMEM);

    dim3 gg(16, 16);

    avgpool_kernel<<<NR * DD / 128, 256>>>(x, A);
    f2b_kernel<<<DD * DD / 2048, 256>>>(Wt, Wtb);
    f2b_kernel<<<DD * DD / 2048, 256>>>(Wr, Wrb);

    // ---- layer 1 ----
    normalize_kernel<<<NR, 256>>>(A, XNb);
    gemm_bf16<0, true, true><<<136, 256, SMEM>>>(XNb, XNb, Mb, nullptr, nullptr);   // cosine
    transpose_kernel<<<dim3(64, 64), dim3(32, 8)>>>(A, ATb);
    gemm_bf16<0, false, false><<<gg, 256, SMEM>>>(Mb, ATb, T, nullptr, nullptr);    // mat @ x
    softmax_kernel<<<NR, 256>>>(T, Tb);
    gemm_bf16<2, false, false><<<gg, 256, SMEM>>>(Tb, Wtb, B, bt, A);               // @Wt^T+bt+x

    // ---- layer 2 ----
    normalize_kernel<<<NR, 256>>>(B, XNb);
    gemm_bf16<0, true, true><<<136, 256, SMEM>>>(XNb, XNb, Mb, nullptr, nullptr);
    transpose_kernel<<<dim3(64, 64), dim3(32, 8)>>>(B, ATb);
    gemm_bf16<0, false, false><<<gg, 256, SMEM>>>(Mb, ATb, T, nullptr, nullptr);
    softmax_kernel<<<NR, 256>>>(T, Tb);
    gemm_bf16<2, false, false><<<gg, 256, SMEM>>>(Tb, Wrb, A, br, B);               // @Wr^T+br+x2

    // ---- heads (partials into T scratch) ----
    head_partial<<<dim3(64, 8), 256>>>(A, Wc, Wb, T);
    head_reduce<<<(NR * 45 + 255) / 256, 256>>>(T, bc, bb, out);
}

// round 8
// speedup vs baseline: 1.0396x; 1.0232x over previous
#include <cuda_runtime.h>
#include <cuda_bf16.h>
#include <math.h>
#include <stddef.h>
#include <stdint.h>

#define NR 2048
#define DD 2048
#define NCLS 9
#define NBB 36

// ---- scratch (device globals: allocation-free rule) ----
__device__ float g_A[NR * DD];                 // feat / x3 (fp32, residual)
__device__ float g_B[NR * DD];                 // x2 (fp32, residual)
__device__ float g_T[NR * DD];                 // mat@x (fp32) ; reused as head partials
__device__ __nv_bfloat16 g_XNb[NR * DD];       // normalized feats (bf16)
__device__ __nv_bfloat16 g_Mb[NR * NR];        // cosine matrix (bf16)
__device__ __nv_bfloat16 g_ATb[NR * DD];       // x^T (bf16)
__device__ __nv_bfloat16 g_Tb[NR * DD];        // softmax(mat@x) (bf16)
__device__ __nv_bfloat16 g_Wtb[DD * DD];       // Wt (bf16)
__device__ __nv_bfloat16 g_Wrb[DD * DD];       // Wr (bf16)

// =====================================================================
// helpers
// =====================================================================
__device__ __forceinline__ uint32_t smem_u32(const void* p) {
    uint32_t a;
    asm("{ .reg .u64 t; cvta.to.shared.u64 t, %1; cvt.u32.u64 %0, t; }"
        : "=r"(a) : "l"(p));
    return a;
}
__device__ __forceinline__ uint32_t pack2(float lo, float hi) {
    uint32_t r;
    asm("cvt.rn.bf16x2.f32 %0, %1, %2;" : "=r"(r) : "f"(hi), "f"(lo));
    return r;
}
#define CP_ASYNC16(dst, src) \
    asm volatile("cp.async.ca.shared.global [%0], [%1], 16;" :: "r"(dst), "l"(src) : "memory")
#define CP_COMMIT() asm volatile("cp.async.commit_group;" ::: "memory")
#define CP_WAIT(n)  asm volatile("cp.async.wait_group %0;" :: "n"(n) : "memory")
#define LDMATRIX_X4(r, addr)                                              \
    asm volatile("ldmatrix.sync.aligned.m8n8.x4.shared.b16 "              \
                 "{%0,%1,%2,%3}, [%4];"                                   \
                 : "=r"((r)[0]), "=r"((r)[1]), "=r"((r)[2]), "=r"((r)[3]) \
                 : "r"(addr))

__device__ __forceinline__ void mma_bf16(float* c, const uint32_t* a, const uint32_t* b) {
    asm volatile(
        "mma.sync.aligned.m16n8k16.row.col.f32.bf16.bf16.f32 "
        "{%0,%1,%2,%3}, {%4,%5,%6,%7}, {%8,%9}, {%0,%1,%2,%3};"
        : "+f"(c[0]), "+f"(c[1]), "+f"(c[2]), "+f"(c[3])
        : "r"(a[0]), "r"(a[1]), "r"(a[2]), "r"(a[3]), "r"(b[0]), "r"(b[1]));
}

// =====================================================================
// AvgPool2d(7,7): [N, D, 7, 7] -> [N, D]  (HBM-bound floor)
// =====================================================================
__global__ void avgpool_kernel(const float* __restrict__ x, float* __restrict__ out) {
    __shared__ float s[128 * 49];
    size_t block0 = (size_t)blockIdx.x * 128;
    const float4* src = reinterpret_cast<const float4*>(x + block0 * 49);
    float4* dst = reinterpret_cast<float4*>(s);
    for (int i = threadIdx.x; i < 128 * 49 / 4; i += 256) dst[i] = src[i];
    __syncthreads();
    if (threadIdx.x < 128) {
        float sum = 0.f;
        #pragma unroll
        for (int k = 0; k < 49; k++) sum += s[threadIdx.x * 49 + k];
        out[block0 + threadIdx.x] = sum * (1.f / 49.f);
    }
}

// =====================================================================
// fp32 -> bf16 convert (weights)
// =====================================================================
__global__ void f2b_kernel(const float* __restrict__ in, __nv_bfloat16* __restrict__ out) {
    size_t i = ((size_t)blockIdx.x * 256 + threadIdx.x) * 8;
    const float4 a = *(const float4*)(in + i);
    const float4 b = *(const float4*)(in + i + 4);
    uint4 o;
    o.x = pack2(a.x, a.y); o.y = pack2(a.z, a.w);
    o.z = pack2(b.x, b.y); o.w = pack2(b.z, b.w);
    *(uint4*)(out + i) = o;
}

// =====================================================================
// Row L2-normalize -> bf16
// =====================================================================
__global__ void normalize_kernel(const float* __restrict__ f, __nv_bfloat16* __restrict__ fn) {
    __shared__ float red[256];
    int row = blockIdx.x, t = threadIdx.x;
    const float4* p = reinterpret_cast<const float4*>(f + (size_t)row * DD);
    float4 v0 = p[2 * t], v1 = p[2 * t + 1];
    float s = v0.x * v0.x + v0.y * v0.y + v0.z * v0.z + v0.w * v0.w
            + v1.x * v1.x + v1.y * v1.y + v1.z * v1.z + v1.w * v1.w;
    red[t] = s;
    __syncthreads();
    for (int o = 128; o; o >>= 1) {
        if (t < o) red[t] += red[t + o];
        __syncthreads();
    }
    float inv = 1.f / fmaxf(sqrtf(red[0]), 1e-8f);
    uint4 o;
    o.x = pack2(v0.x * inv, v0.y * inv);
    o.y = pack2(v0.z * inv, v0.w * inv);
    o.z = pack2(v1.x * inv, v1.y * inv);
    o.w = pack2(v1.z * inv, v1.w * inv);
    *(uint4*)(fn + (size_t)row * DD + t * 8) = o;
}

// =====================================================================
// Row softmax: fp32 in -> bf16 out
// =====================================================================
__global__ void softmax_kernel(const float* __restrict__ in, __nv_bfloat16* __restrict__ outb) {
    __shared__ float red[256];
    int row = blockIdx.x, t = threadIdx.x;
    const float4* p = reinterpret_cast<const float4*>(in + (size_t)row * NR);
    float4 u0 = p[2 * t], u1 = p[2 * t + 1];
    float v[8] = {u0.x, u0.y, u0.z, u0.w, u1.x, u1.y, u1.z, u1.w};
    float mx = v[0];
    #pragma unroll
    for (int i = 1; i < 8; i++) mx = fmaxf(mx, v[i]);
    red[t] = mx;
    __syncthreads();
    for (int o = 128; o; o >>= 1) {
        if (t < o) red[t] = fmaxf(red[t], red[t + o]);
        __syncthreads();
    }
    mx = red[0];
    __syncthreads();
    float s = 0.f;
    #pragma unroll
    for (int i = 0; i < 8; i++) {
        v[i] = __expf(v[i] - mx);
        s += v[i];
    }
    red[t] = s;
    __syncthreads();
    for (int o = 128; o; o >>= 1) {
        if (t < o) red[t] += red[t + o];
        __syncthreads();
    }
    float inv = 1.f / red[0];
    uint4 o;
    o.x = pack2(v[0] * inv, v[1] * inv);
    o.y = pack2(v[2] * inv, v[3] * inv);
    o.z = pack2(v[4] * inv, v[5] * inv);
    o.w = pack2(v[6] * inv, v[7] * inv);
    *(uint4*)(outb + (size_t)row * NR + t * 8) = o;
}

// =====================================================================
// 32x32 tiled transpose: out(bf16) = in(fp32)^T
// =====================================================================
__global__ void transpose_kernel(const float* __restrict__ in, __nv_bfloat16* __restrict__ out) {
    __shared__ float tile[32][33];
    int x = blockIdx.x * 32 + threadIdx.x;
    int y = blockIdx.y * 32 + threadIdx.y;
    #pragma unroll
    for (int j = 0; j < 32; j += 8)
        tile[threadIdx.y + j][threadIdx.x] = in[(size_t)(y + j) * DD + x];
    __syncthreads();
    x = blockIdx.y * 32 + threadIdx.x;
    y = blockIdx.x * 32 + threadIdx.y;
    #pragma unroll
    for (int j = 0; j < 32; j += 8)
        out[(size_t)(y + j) * DD + x] = __float2bfloat16_rn(tile[threadIdx.x][threadIdx.y + j]);
}

// =====================================================================
// Cosine GEMM (round-5 proven): 128x128 tile, 2-stage, bf16 sym out.
// =====================================================================
#define STG 16384

__device__ __forceinline__ void load_stage_sq(uint32_t sb32,
                                              const __nv_bfloat16* A, const __nv_bfloat16* B,
                                              int bm0, int bn0, int k0, int buf, int t) {
    const int ch = t & 7;
    const int r0 = t >> 3;
    const uint32_t abase = sb32 + (uint32_t)buf * (2 * STG);
    #pragma unroll
    for (int p = 0; p < 4; p++) {
        const int row = r0 + p * 32;
        uint32_t o = (uint32_t)row * 128 + ch * 16;
        uint32_t sw = o ^ ((o >> 3) & 0x70);
        CP_ASYNC16(abase + sw, A + (size_t)(bm0 + row) * DD + k0 + ch * 8);
        CP_ASYNC16(abase + STG + sw, B + (size_t)(bn0 + row) * DD + k0 + ch * 8);
    }
}

__global__ __launch_bounds__(256, 2)
void gemm_cos(const __nv_bfloat16* __restrict__ XN, __nv_bfloat16* __restrict__ C) {
    extern __shared__ char dynsm[];
    char* sb = (char*)(((uintptr_t)dynsm + 1023) & ~(uintptr_t)1023);
    const uint32_t sb32 = smem_u32(sb);
    const int t = threadIdx.x;
    const int lane = t & 31, wid = t >> 5;
    const int wm = (wid & 3) * 32;
    const int wn = (wid >> 2) * 64;

    int rem = blockIdx.x, i = 0;
    while (rem >= 16 - i) { rem -= 16 - i; i++; }
    const int bm0 = i * 128;
    const int bn0 = (i + rem) * 128;

    float acc[2][8][4];
    #pragma unroll
    for (int a = 0; a < 2; a++)
        #pragma unroll
        for (int b = 0; b < 8; b++)
            #pragma unroll
            for (int q = 0; q < 4; q++) acc[a][b][q] = 0.f;

    load_stage_sq(sb32, XN, XN, bm0, bn0, 0, 0, t);
    CP_COMMIT();

    const int a_row_l = lane & 15;
    const int a_kb = (lane >> 4) * 16;
    const int b_row_l = ((lane >> 4) << 3) + (lane & 7);
    const int b_kb = ((lane >> 3) & 1) * 16;

    for (int s = 0; s < 32; s++) {
        if (s < 31) {
            load_stage_sq(sb32, XN, XN, bm0, bn0, (s + 1) * 64, (s + 1) & 1, t);
            CP_COMMIT();
            CP_WAIT(1);
        } else {
            CP_WAIT(0);
        }
        __syncthreads();
        const uint32_t aB = sb32 + (uint32_t)(s & 1) * (2 * STG);
        const uint32_t bB = aB + STG;
        #pragma unroll
        for (int kk = 0; kk < 4; kk++) {
            const int kb = kk * 32;
            uint32_t af[2][4], bf[4][4];
            #pragma unroll
            for (int mt = 0; mt < 2; mt++) {
                uint32_t o = (uint32_t)(wm + mt * 16 + a_row_l) * 128 + kb + a_kb;
                LDMATRIX_X4(af[mt], aB + (o ^ ((o >> 3) & 0x70)));
            }
            #pragma unroll
            for (int nt2 = 0; nt2 < 4; nt2++) {
                uint32_t o = (uint32_t)(wn + nt2 * 16 + b_row_l) * 128 + kb + b_kb;
                LDMATRIX_X4(bf[nt2], bB + (o ^ ((o >> 3) & 0x70)));
            }
            #pragma unroll
            for (int mt = 0; mt < 2; mt++)
                #pragma unroll
                for (int nt2 = 0; nt2 < 4; nt2++) {
                    mma_bf16(acc[mt][nt2 * 2 + 0], af[mt], &bf[nt2][0]);
                    mma_bf16(acc[mt][nt2 * 2 + 1], af[mt], &bf[nt2][2]);
                }
        }
        __syncthreads();
    }

    const int g = lane >> 2;
    const int c2 = (lane & 3) * 2;
    #pragma unroll
    for (int mt = 0; mt < 2; mt++) {
        const int row0 = bm0 + wm + mt * 16 + g;
        #pragma unroll
        for (int nt = 0; nt < 8; nt++) {
            const int col0 = bn0 + wn + nt * 8 + c2;
            float v0 = acc[mt][nt][0], v1 = acc[mt][nt][1];
            float v2 = acc[mt][nt][2], v3 = acc[mt][nt][3];
            *(uint32_t*)&C[(size_t)row0 * DD + col0] = pack2(v0, v1);
            *(uint32_t*)&C[(size_t)(row0 + 8) * DD + col0] = pack2(v2, v3);
            if (bm0 != bn0) {
                C[(size_t)col0 * DD + row0] = __float2bfloat16_rn(v0);
                C[(size_t)(col0 + 1) * DD + row0] = __float2bfloat16_rn(v1);
                C[(size_t)col0 * DD + row0 + 8] = __float2bfloat16_rn(v2);
                C[(size_t)(col0 + 1) * DD + row0 + 8] = __float2bfloat16_rn(v3);
            }
        }
    }
}

// =====================================================================
// BIG bf16 NT GEMM: 256x128 CTA tile, 8 warps @ 64x64, BK=64, 3-stage,
// 1 CTA/SM, single barrier per stage. C[m,n] = sum_k A[m,k]*B[n,k].
// EPI: 0 plain fp32 | 2 (+bias[c]+res[r,c]) fp32.
// =====================================================================
#define BSTG 49152           // bytes per stage: A 32KB + B 16KB
#define NSTAGE 3

__device__ __forceinline__ void load_stage_big(uint32_t sb32,
                                               const __nv_bfloat16* A, const __nv_bfloat16* B,
                                               int bm0, int bn0, int k0, int buf, int t) {
    const int ch = t & 7;        // 16B chunk within 128B row
    const int r0 = t >> 3;       // 0..31
    const uint32_t base = sb32 + (uint32_t)buf * BSTG;
    #pragma unroll
    for (int p = 0; p < 8; p++) {            // A: 256 rows
        const int row = r0 + p * 32;
        uint32_t o = (uint32_t)row * 128 + ch * 16;
        CP_ASYNC16(base + (o ^ ((o >> 3) & 0x70)),
                   A + (size_t)(bm0 + row) * DD + k0 + ch * 8);
    }
    #pragma unroll
    for (int p = 0; p < 4; p++) {            // B: 128 rows
        const int row = r0 + p * 32;
        uint32_t o = (uint32_t)row * 128 + ch * 16;
        CP_ASYNC16(base + 32768u + (o ^ ((o >> 3) & 0x70)),
                   B + (size_t)(bn0 + row) * DD + k0 + ch * 8);
    }
}

template <int EPI>
__global__ __launch_bounds__(256, 1)
void gemm_big(const __nv_bfloat16* __restrict__ A, const __nv_bfloat16* __restrict__ B,
              float* __restrict__ C,
              const float* __restrict__ bias,
              const float* __restrict__ res) {
    extern __shared__ char dynsm[];
    char* sb = (char*)(((uintptr_t)dynsm + 1023) & ~(uintptr_t)1023);
    const uint32_t sb32 = smem_u32(sb);

    const int t = threadIdx.x;
    const int lane = t & 31, wid = t >> 5;
    const int wm = (wid & 3) * 64;       // 4 warp-rows of 64
    const int wn = (wid >> 2) * 64;      // 2 warp-cols of 64
    const int bm0 = blockIdx.y * 256;
    const int bn0 = blockIdx.x * 128;

    float acc[4][8][4];
    #pragma unroll
    for (int i = 0; i < 4; i++)
        #pragma unroll
        for (int j = 0; j < 8; j++)
            #pragma unroll
            for (int q = 0; q < 4; q++) acc[i][j][q] = 0.f;

    load_stage_big(sb32, A, B, bm0, bn0, 0, 0, t);
    CP_COMMIT();
    load_stage_big(sb32, A, B, bm0, bn0, 64, 1, t);
    CP_COMMIT();

    const int a_row_l = lane & 15;
    const int a_kb = (lane >> 4) * 16;
    const int b_row_l = ((lane >> 4) << 3) + (lane & 7);
    const int b_kb = ((lane >> 3) & 1) * 16;

    int buf = 0;
    for (int s = 0; s < 32; s++) {
        if (s < 31) { CP_WAIT(1); } else { CP_WAIT(0); }
        __syncthreads();
        if (s < 30) {
            int nb = buf + 2; if (nb >= NSTAGE) nb -= NSTAGE;
            load_stage_big(sb32, A, B, bm0, bn0, (s + 2) * 64, nb, t);
            CP_COMMIT();
        }

        const uint32_t aB = sb32 + (uint32_t)buf * BSTG;
        const uint32_t bB = aB + 32768u;
        #pragma unroll
        for (int kk = 0; kk < 4; kk++) {
            const int kb = kk * 32;
            uint32_t af[4][4], bf[4][4];
            #pragma unroll
            for (int mt = 0; mt < 4; mt++) {
                uint32_t o = (uint32_t)(wm + mt * 16 + a_row_l) * 128 + kb + a_kb;
                LDMATRIX_X4(af[mt], aB + (o ^ ((o >> 3) & 0x70)));
            }
            #pragma unroll
            for (int nt2 = 0; nt2 < 4; nt2++) {
                uint32_t o = (uint32_t)(wn + nt2 * 16 + b_row_l) * 128 + kb + b_kb;
                LDMATRIX_X4(bf[nt2], bB + (o ^ ((o >> 3) & 0x70)));
            }
            #pragma unroll
            for (int mt = 0; mt < 4; mt++)
                #pragma unroll
                for (int nt2 = 0; nt2 < 4; nt2++) {
                    mma_bf16(acc[mt][nt2 * 2 + 0], af[mt], &bf[nt2][0]);
                    mma_bf16(acc[mt][nt2 * 2 + 1], af[mt], &bf[nt2][2]);
                }
        }
        if (++buf == NSTAGE) buf = 0;
    }

    // ---- epilogue ----
    const int g = lane >> 2;
    const int c2 = (lane & 3) * 2;
    #pragma unroll
    for (int mt = 0; mt < 4; mt++) {
        const int row0 = bm0 + wm + mt * 16 + g;
        #pragma unroll
        for (int nt = 0; nt < 8; nt++) {
            const int col0 = bn0 + wn + nt * 8 + c2;
            float v0 = acc[mt][nt][0], v1 = acc[mt][nt][1];
            float v2 = acc[mt][nt][2], v3 = acc[mt][nt][3];
            if (EPI == 2) {
                float b0 = bias[col0], b1 = bias[col0 + 1];
                const float2 r0 = *(const float2*)&res[(size_t)row0 * DD + col0];
                const float2 r1 = *(const float2*)&res[(size_t)(row0 + 8) * DD + col0];
                v0 += b0 + r0.x; v1 += b1 + r0.y;
                v2 += b0 + r1.x; v3 += b1 + r1.y;
            }
            float2 o0 = {v0, v1}, o1 = {v2, v3};
            *(float2*)&C[(size_t)row0 * DD + col0] = o0;
            *(float2*)&C[(size_t)(row0 + 8) * DD + col0] = o1;
        }
    }
}

// =====================================================================
// Head, split-K
// =====================================================================
__global__ __launch_bounds__(256)
void head_partial(const float* __restrict__ x,
                  const float* __restrict__ Wc, const float* __restrict__ Wb,
                  float* __restrict__ part) {
    __shared__ float Wsm[48 * 64];
    __shared__ float xs[32 * 65];
    const int rb = blockIdx.x, ks = blockIdx.y;
    const int t = threadIdx.x;
    const int r = t & 31, jg = t >> 5;

    float acc[6] = {0.f, 0.f, 0.f, 0.f, 0.f, 0.f};

    for (int k0 = ks * 256; k0 < ks * 256 + 256; k0 += 64) {
        for (int i = t; i < 45 * 64; i += 256) {
            int j = i >> 6, k = i & 63;
            const float* w = (j < NCLS) ? (Wc + (size_t)j * DD)
                                        : (Wb + (size_t)(j - NCLS) * DD);
            Wsm[i] = w[k0 + k];
        }
        for (int i = t; i < 32 * 64; i += 256) {
            int rr = i >> 6, k = i & 63;
            xs[rr * 65 + k] = x[(size_t)(rb * 32 + rr) * DD + k0 + k];
        }
        __syncthreads();
        #pragma unroll 4
        for (int k = 0; k < 64; k++) {
            float xv = xs[r * 65 + k];
            #pragma unroll
            for (int u = 0; u < 6; u++) {
                int j = jg + 8 * u;
                if (j < 45) acc[u] += xv * Wsm[j * 64 + k];
            }
        }
        __syncthreads();
    }
    #pragma unroll
    for (int u = 0; u < 6; u++) {
        int j = jg + 8 * u;
        if (j < 45)
            part[((size_t)ks * NR + rb * 32 + r) * 45 + j] = acc[u];
    }
}

__global__ void head_reduce(const float* __restrict__ part,
                            const float* __restrict__ bc, const float* __restrict__ bb,
                            float* __restrict__ out) {
    int idx = blockIdx.x * 256 + threadIdx.x;
    if (idx >= NR * 45) return;
    int i = idx / 45, j = idx - i * 45;
    float s = 0.f;
    #pragma unroll
    for (int ks = 0; ks < 8; ks++) s += part[((size_t)ks * NR + i) * 45 + j];
    if (j < NCLS)
        out[(size_t)i * NCLS + j] = s + bc[j];
    else
        out[(size_t)NR * NCLS + (size_t)i * NBB + (j - NCLS)] = s + bb[j - NCLS];
}

// =====================================================================
extern "C" void kernel_launch(void* const* d_in, const int* in_sizes, int n_in,
                              void* d_out, int out_size) {
    const float* x  = (const float*)d_in[0];
    const float* Wt = (const float*)d_in[1];
    const float* bt = (const float*)d_in[2];
    const float* Wr = (const float*)d_in[3];
    const float* br = (const float*)d_in[4];
    const float* Wc = (const float*)d_in[5];
    const float* bc = (const float*)d_in[6];
    const float* Wb = (const float*)d_in[7];
    const float* bb = (const float*)d_in[8];
    float* out = (float*)d_out;

    float *A, *B, *T;
    __nv_bfloat16 *XNb, *Mb, *ATb, *Tb, *Wtb, *Wrb;
    cudaGetSymbolAddress((void**)&A, g_A);
    cudaGetSymbolAddress((void**)&B, g_B);
    cudaGetSymbolAddress((void**)&T, g_T);
    cudaGetSymbolAddress((void**)&XNb, g_XNb);
    cudaGetSymbolAddress((void**)&Mb, g_Mb);
    cudaGetSymbolAddress((void**)&ATb, g_ATb);
    cudaGetSymbolAddress((void**)&Tb, g_Tb);
    cudaGetSymbolAddress((void**)&Wtb, g_Wtb);
    cudaGetSymbolAddress((void**)&Wrb, g_Wrb);

    const int SMEM_SQ  = 4 * STG + 1024;          // 66560 B  (cosine)
    const int SMEM_BIG = NSTAGE * BSTG + 1024;    // 148480 B (big)
    cudaFuncSetAttribute(gemm_cos, cudaFuncAttributeMaxDynamicSharedMemorySize, SMEM_SQ);
    cudaFuncSetAttribute(gemm_big<0>, cudaFuncAttributeMaxDynamicSharedMemorySize, SMEM_BIG);
    cudaFuncSetAttribute(gemm_big<2>, cudaFuncAttributeMaxDynamicSharedMemorySize, SMEM_BIG);

    dim3 gbig(16, 8);   // n blocks (128) x m blocks (256)

    avgpool_kernel<<<NR * DD / 128, 256>>>(x, A);
    f2b_kernel<<<DD * DD / 2048, 256>>>(Wt, Wtb);
    f2b_kernel<<<DD * DD / 2048, 256>>>(Wr, Wrb);

    // ---- layer 1 ----
    normalize_kernel<<<NR, 256>>>(A, XNb);
    gemm_cos<<<136, 256, SMEM_SQ>>>(XNb, Mb);                                 // cosine
    transpose_kernel<<<dim3(64, 64), dim3(32, 8)>>>(A, ATb);
    gemm_big<0><<<gbig, 256, SMEM_BIG>>>(Mb, ATb, T, nullptr, nullptr);       // mat @ x
    softmax_kernel<<<NR, 256>>>(T, Tb);
    gemm_big<2><<<gbig, 256, SMEM_BIG>>>(Tb, Wtb, B, bt, A);                  // @Wt^T+bt+x

    // ---- layer 2 ----
    normalize_kernel<<<NR, 256>>>(B, XNb);
    gemm_cos<<<136, 256, SMEM_SQ>>>(XNb, Mb);
    transpose_kernel<<<dim3(64, 64), dim3(32, 8)>>>(B, ATb);
    gemm_big<0><<<gbig, 256, SMEM_BIG>>>(Mb, ATb, T, nullptr, nullptr);
    softmax_kernel<<<NR, 256>>>(T, Tb);
    gemm_big<2><<<gbig, 256, SMEM_BIG>>>(Tb, Wrb, A, br, B);                  // @Wr^T+br+x2

    // ---- heads (partials into T scratch) ----
    head_partial<<<dim3(64, 8), 256>>>(A, Wc, Wb, T);
    head_reduce<<<(NR * 45 + 255) / 256, 256>>>(T, bc, bb, out);
}